// round 1
// baseline (speedup 1.0000x reference)
#include <cuda_runtime.h>
#include <cuda_bf16.h>
#include <math.h>

// ---------------------------------------------------------------------------
// Problem dims (from reference): N=50000 nodes, E=1.6M edges,
// nfeat=256, nhid=512, nclass=128, next=64.
// Pipeline (reassociated):
//   AX  = spmm(adj, x)                      [N,256]   (A@(X@W1) == (A@X)@W1)
//   h1  = selu(AX @ W1 + b1)                [N,512]
//   H2  = h1 @ W2                           [N,128]
//   S2  = spmm(adj, H2)                     [N,128]
//   cs  = colsum(selu(S2 + b2))             [128]     (h2 never materialized)
//   g   = selu(cs/N); gcat=[g, sub_fea]; logits=gcat@Wf+bf; logp; l1=mean|Wf|
// ---------------------------------------------------------------------------

#define MAX_N 50000
__device__ float g_AX[MAX_N * 256];   // 51.2 MB
__device__ float g_H1[MAX_N * 512];   // 102.4 MB
__device__ float g_H2[MAX_N * 128];   // 25.6 MB
__device__ float g_S2[MAX_N * 128];   // 25.6 MB
__device__ float g_CS[128];

__device__ __forceinline__ float selu_f(float x) {
    const float scale = 1.0507009873554804934769f;
    const float alpha = 1.6732632423543772848170f;
    return x > 0.0f ? scale * x : scale * alpha * expm1f(x);
}

// ---------------------------------------------------------------------------
// SpMM: one warp per edge. out[row] += val * dense[col]  (F floats per row)
// 16B vector reductions to cut LTS atomic op count 4x.
// ---------------------------------------------------------------------------
template <int F>
__global__ void spmm_kernel(const int* __restrict__ rows,
                            const int* __restrict__ cols,
                            const float* __restrict__ vals,
                            const float* __restrict__ dense,
                            float* __restrict__ outbuf, int E) {
    int gw = (int)((blockIdx.x * blockDim.x + threadIdx.x) >> 5);
    if (gw >= E) return;
    int lane = threadIdx.x & 31;
    int r = __ldg(rows + gw);
    int c = __ldg(cols + gw);
    float v = __ldg(vals + gw);
    const float4* src = (const float4*)(dense + (size_t)c * F);
    float* dst = outbuf + (size_t)r * F;
#pragma unroll
    for (int i = lane; i < F / 4; i += 32) {
        float4 d = __ldg(src + i);
        asm volatile("red.global.add.v4.f32 [%0], {%1,%2,%3,%4};"
                     :: "l"(dst + 4 * i),
                        "f"(v * d.x), "f"(v * d.y), "f"(v * d.z), "f"(v * d.w)
                     : "memory");
    }
}

// ---------------------------------------------------------------------------
// fp32 tiled GEMM: C[M,N] = A[M,K] @ B[K,N] (+bias) (+selu)
// 64x64 tile, BK=16, 256 threads, 4x4 per thread, float4 smem traffic.
// N % 64 == 0, K % 16 == 0 guaranteed (512/128, 256/512). M guarded.
// ---------------------------------------------------------------------------
__global__ void gemm64_kernel(const float* __restrict__ A,
                              const float* __restrict__ B,
                              const float* __restrict__ bias,
                              float* __restrict__ C,
                              int M, int N, int K, int doSelu) {
    __shared__ float As[16][68];
    __shared__ float Bs[16][68];
    int t = threadIdx.x;
    int tn = t & 15, tm = t >> 4;
    int m0 = blockIdx.y * 64, n0 = blockIdx.x * 64;

    int lm  = t >> 2;   // 0..63: A row within tile
    int lk4 = t & 3;    // 0..3 : A float4 chunk within K-slab
    int lkB = t >> 4;   // 0..15: B row within K-slab
    int lnB = t & 15;   // 0..15: B float4 col

    float acc[4][4] = {};

    for (int k0 = 0; k0 < K; k0 += 16) {
        float4 a = make_float4(0.f, 0.f, 0.f, 0.f);
        if (m0 + lm < M)
            a = *(const float4*)&A[(size_t)(m0 + lm) * K + k0 + lk4 * 4];
        As[lk4 * 4 + 0][lm] = a.x;
        As[lk4 * 4 + 1][lm] = a.y;
        As[lk4 * 4 + 2][lm] = a.z;
        As[lk4 * 4 + 3][lm] = a.w;
        float4 b = *(const float4*)&B[(size_t)(k0 + lkB) * N + n0 + lnB * 4];
        *(float4*)&Bs[lkB][lnB * 4] = b;
        __syncthreads();
#pragma unroll
        for (int k = 0; k < 16; k++) {
            float4 av = *(const float4*)&As[k][tm * 4];
            float4 bv = *(const float4*)&Bs[k][tn * 4];
            float am[4] = {av.x, av.y, av.z, av.w};
            float bn[4] = {bv.x, bv.y, bv.z, bv.w};
#pragma unroll
            for (int i = 0; i < 4; i++)
#pragma unroll
                for (int j = 0; j < 4; j++)
                    acc[i][j] = fmaf(am[i], bn[j], acc[i][j]);
        }
        __syncthreads();
    }

    float4 b4 = make_float4(0.f, 0.f, 0.f, 0.f);
    if (bias) b4 = *(const float4*)&bias[n0 + tn * 4];
    float bb[4] = {b4.x, b4.y, b4.z, b4.w};
#pragma unroll
    for (int i = 0; i < 4; i++) {
        int m = m0 + tm * 4 + i;
        if (m < M) {
            float4 v;
            float r0 = acc[i][0] + bb[0];
            float r1 = acc[i][1] + bb[1];
            float r2 = acc[i][2] + bb[2];
            float r3 = acc[i][3] + bb[3];
            if (doSelu) {
                r0 = selu_f(r0); r1 = selu_f(r1); r2 = selu_f(r2); r3 = selu_f(r3);
            }
            v.x = r0; v.y = r1; v.z = r2; v.w = r3;
            *(float4*)&C[(size_t)m * N + n0 + tn * 4] = v;
        }
    }
}

// ---------------------------------------------------------------------------
// Column sums of selu(S2 + b2) over all rows. 128 threads = 128 columns.
// ---------------------------------------------------------------------------
__global__ void selu_colsum_kernel(const float* __restrict__ S2,
                                   const float* __restrict__ b2,
                                   float* __restrict__ colsum, int M) {
    int t = threadIdx.x;  // 0..127
    int r0 = blockIdx.x * 128;
    int rend = min(r0 + 128, M);
    float b = b2[t];
    float s = 0.f;
    for (int r = r0; r < rend; r++)
        s += selu_f(S2[(size_t)r * 128 + t] + b);
    atomicAdd(&colsum[t], s);
}

// ---------------------------------------------------------------------------
// Head: g = selu(colsum/M); gcat = [g, sub_fea]; logits = gcat@Wf + bf;
// logp = log_softmax(logits); l1 = mean(|Wf|). Single block, 128 threads.
// ---------------------------------------------------------------------------
__global__ void final_kernel(const float* __restrict__ colsum,
                             const float* __restrict__ sub_fea,
                             const float* __restrict__ Wf,
                             const float* __restrict__ bf,
                             float* __restrict__ out, int M) {
    __shared__ float gcat[192];
    __shared__ float sred[4];
    int t = threadIdx.x;  // 0..127
    gcat[t] = selu_f(colsum[t] / (float)M);
    if (t < 64) gcat[128 + t] = sub_fea[t];
    __syncthreads();

    float logit = bf[t];
#pragma unroll 8
    for (int i = 0; i < 192; i++)
        logit = fmaf(gcat[i], Wf[i * 128 + t], logit);

    // max over 128
    float mx = logit;
    for (int o = 16; o; o >>= 1) mx = fmaxf(mx, __shfl_xor_sync(0xffffffffu, mx, o));
    if ((t & 31) == 0) sred[t >> 5] = mx;
    __syncthreads();
    mx = fmaxf(fmaxf(sred[0], sred[1]), fmaxf(sred[2], sred[3]));
    __syncthreads();

    // sum exp
    float e = expf(logit - mx);
    float se = e;
    for (int o = 16; o; o >>= 1) se += __shfl_xor_sync(0xffffffffu, se, o);
    if ((t & 31) == 0) sred[t >> 5] = se;
    __syncthreads();
    se = sred[0] + sred[1] + sred[2] + sred[3];
    out[t] = logit - mx - logf(se);
    __syncthreads();

    // l1 over 192*128 = 24576 elems
    float l = 0.f;
    for (int i = t; i < 24576; i += 128) l += fabsf(Wf[i]);
    for (int o = 16; o; o >>= 1) l += __shfl_xor_sync(0xffffffffu, l, o);
    if ((t & 31) == 0) sred[t >> 5] = l;
    __syncthreads();
    if (t == 0) out[128] = (sred[0] + sred[1] + sred[2] + sred[3]) / 24576.0f;
}

// ---------------------------------------------------------------------------
extern "C" void kernel_launch(void* const* d_in, const int* in_sizes, int n_in,
                              void* d_out, int out_size) {
    const float* x       = (const float*)d_in[0];
    const int*   adj     = (const int*)  d_in[1];
    const float* vals    = (const float*)d_in[2];
    const float* sub_fea = (const float*)d_in[3];
    const float* W1      = (const float*)d_in[4];
    const float* b1      = (const float*)d_in[5];
    const float* W2      = (const float*)d_in[6];
    const float* b2      = (const float*)d_in[7];
    const float* Wf      = (const float*)d_in[8];
    const float* bf      = (const float*)d_in[9];
    float* out = (float*)d_out;

    int E = in_sizes[2];
    int M = in_sizes[0] / 256;

    float *pAX, *pH1, *pH2, *pS2, *pCS;
    cudaGetSymbolAddress((void**)&pAX, g_AX);
    cudaGetSymbolAddress((void**)&pH1, g_H1);
    cudaGetSymbolAddress((void**)&pH2, g_H2);
    cudaGetSymbolAddress((void**)&pS2, g_S2);
    cudaGetSymbolAddress((void**)&pCS, g_CS);

    cudaMemsetAsync(pAX, 0, (size_t)M * 256 * sizeof(float));
    cudaMemsetAsync(pS2, 0, (size_t)M * 128 * sizeof(float));
    cudaMemsetAsync(pCS, 0, 128 * sizeof(float));

    int spmmBlocks = (E + 7) / 8;  // 8 warps per 256-thread block, 1 warp/edge
    // AX = spmm(adj, x)  [M,256]
    spmm_kernel<256><<<spmmBlocks, 256>>>(adj, adj + E, vals, x, pAX, E);
    // h1 = selu(AX @ W1 + b1)  [M,512]
    dim3 g1(512 / 64, (M + 63) / 64);
    gemm64_kernel<<<g1, 256>>>(pAX, W1, b1, pH1, M, 512, 256, 1);
    // H2 = h1 @ W2  [M,128]
    dim3 g2(128 / 64, (M + 63) / 64);
    gemm64_kernel<<<g2, 256>>>(pH1, W2, nullptr, pH2, M, 128, 512, 0);
    // S2 = spmm(adj, H2)  [M,128]
    spmm_kernel<128><<<spmmBlocks, 256>>>(adj, adj + E, vals, pH2, pS2, E);
    // colsum(selu(S2 + b2))
    selu_colsum_kernel<<<(M + 127) / 128, 128>>>(pS2, b2, pCS, M);
    // head
    final_kernel<<<1, 128>>>(pCS, sub_fea, Wf, bf, out, M);
}

// round 3
// speedup vs baseline: 1.3673x; 1.3673x over previous
#include <cuda_runtime.h>
#include <cuda_bf16.h>
#include <math.h>

// ---------------------------------------------------------------------------
// Pipeline (reassociated):
//   CSR build (hist -> scan -> scatter), shared by both SpMMs
//   AX  = spmm_csr(adj, x)                  [N,256]
//   h1  = selu(AX @ W1 + b1)                [N,512]
//   H2  = h1 @ W2                           [N,128]
//   S2  = spmm_csr(adj, H2)                 [N,128]
//   cs  = colsum(selu(S2 + b2))             [128]
//   head: selu(cs/N), concat, logits, log_softmax, L1
// ---------------------------------------------------------------------------

#define MAX_N 50000
#define MAX_E 1600000

__device__ float g_AX[MAX_N * 256];
__device__ float g_H1[MAX_N * 512];
__device__ float g_H2[MAX_N * 128];
__device__ float g_S2[MAX_N * 128];
__device__ float g_CS[128];

__device__ int   g_count[MAX_N];
__device__ int   g_start[MAX_N + 1];
__device__ int   g_cursor[MAX_N];
__device__ int   g_ecol[MAX_E];
__device__ float g_eval[MAX_E];

__device__ __forceinline__ float selu_f(float x) {
    const float scale = 1.0507009873554804934769f;
    const float alpha = 1.6732632423543772848170f;
    return x > 0.0f ? scale * x : scale * alpha * expm1f(x);
}

// ------------------------------ CSR build ----------------------------------
__global__ void hist_kernel(const int* __restrict__ rows, int E) {
    int e = blockIdx.x * blockDim.x + threadIdx.x;
    if (e < E) atomicAdd(&g_count[rows[e]], 1);
}

__global__ void scan_kernel(int Nn, int E) {
    __shared__ int warpsum[32];
    int t = threadIdx.x;  // 1024 threads
    int chunk = (Nn + 1023) / 1024;
    int lo = t * chunk, hi = min(lo + chunk, Nn);
    int s = 0;
    for (int i = lo; i < hi; i++) s += g_count[i];
    // inclusive warp scan
    int v = s;
    for (int o = 1; o < 32; o <<= 1) {
        int n = __shfl_up_sync(0xffffffffu, v, o);
        if ((t & 31) >= o) v += n;
    }
    if ((t & 31) == 31) warpsum[t >> 5] = v;
    __syncthreads();
    if (t < 32) {
        int w = warpsum[t];
        for (int o = 1; o < 32; o <<= 1) {
            int n = __shfl_up_sync(0xffffffffu, w, o);
            if (t >= o) w += n;
        }
        warpsum[t] = w;
    }
    __syncthreads();
    int excl = v - s + ((t >= 32) ? warpsum[(t >> 5) - 1] : 0);
    int run = excl;
    for (int i = lo; i < hi; i++) {
        g_start[i] = run;
        run += g_count[i];
    }
    if (t == 0) g_start[Nn] = E;
}

__global__ void scatter_kernel(const int* __restrict__ rows,
                               const int* __restrict__ cols,
                               const float* __restrict__ vals, int E) {
    int e = blockIdx.x * blockDim.x + threadIdx.x;
    if (e >= E) return;
    int r = rows[e];
    int p = atomicAdd(&g_cursor[r], 1);
    int idx = g_start[r] + p;
    g_ecol[idx] = cols[e];
    g_eval[idx] = vals[e];
}

// ---------------------------- CSR SpMM -------------------------------------
// One warp per row: gather deg edges, accumulate in registers, one write.
template <int F>
__global__ void spmm_csr_kernel(const float* __restrict__ dense,
                                float* __restrict__ out, int Nn) {
    constexpr int V = F / 128;  // float4s per lane
    int row = blockIdx.x * 8 + (int)(threadIdx.x >> 5);
    if (row >= Nn) return;
    int lane = threadIdx.x & 31;
    int s = __ldg(g_start + row), e = __ldg(g_start + row + 1);
    float4 acc[V];
#pragma unroll
    for (int j = 0; j < V; j++) acc[j] = make_float4(0.f, 0.f, 0.f, 0.f);
    int i = s;
    for (; i + 2 <= e; i += 2) {
        int c0 = __ldg(g_ecol + i), c1 = __ldg(g_ecol + i + 1);
        float v0 = __ldg(g_eval + i), v1 = __ldg(g_eval + i + 1);
        const float4* s0 = (const float4*)(dense + (size_t)c0 * F) + lane;
        const float4* s1 = (const float4*)(dense + (size_t)c1 * F) + lane;
#pragma unroll
        for (int j = 0; j < V; j++) {
            float4 d0 = __ldg(s0 + j * 32);
            float4 d1 = __ldg(s1 + j * 32);
            acc[j].x = fmaf(v0, d0.x, fmaf(v1, d1.x, acc[j].x));
            acc[j].y = fmaf(v0, d0.y, fmaf(v1, d1.y, acc[j].y));
            acc[j].z = fmaf(v0, d0.z, fmaf(v1, d1.z, acc[j].z));
            acc[j].w = fmaf(v0, d0.w, fmaf(v1, d1.w, acc[j].w));
        }
    }
    if (i < e) {
        int c0 = __ldg(g_ecol + i);
        float v0 = __ldg(g_eval + i);
        const float4* s0 = (const float4*)(dense + (size_t)c0 * F) + lane;
#pragma unroll
        for (int j = 0; j < V; j++) {
            float4 d0 = __ldg(s0 + j * 32);
            acc[j].x = fmaf(v0, d0.x, acc[j].x);
            acc[j].y = fmaf(v0, d0.y, acc[j].y);
            acc[j].z = fmaf(v0, d0.z, acc[j].z);
            acc[j].w = fmaf(v0, d0.w, acc[j].w);
        }
    }
    float4* o = (float4*)(out + (size_t)row * F) + lane;
#pragma unroll
    for (int j = 0; j < V; j++) o[j * 32] = acc[j];
}

// ---------------------------- GEMM 128x128 ---------------------------------
// C[M,N] = A[M,K] @ B[K,N] (+bias)(+selu). 256 threads, 8x8 per thread,
// split 4+4 at stride 64 for conflict-free LDS.128. N%128==0, K%16==0.
__global__ void gemm128_kernel(const float* __restrict__ A,
                               const float* __restrict__ B,
                               const float* __restrict__ bias,
                               float* __restrict__ C,
                               int M, int N, int K, int doSelu) {
    __shared__ float As[16][132];
    __shared__ float Bs[16][132];
    int t = threadIdx.x;
    int tm = t >> 4, tn = t & 15;  // 16x16 threads
    int m0 = blockIdx.y * 128, n0 = blockIdx.x * 128;

    float acc[8][8] = {};

    for (int k0 = 0; k0 < K; k0 += 16) {
        // load A tile: 128 rows x 16 k = 512 float4; 2 per thread (transposed)
#pragma unroll
        for (int l = 0; l < 2; l++) {
            int c = t + l * 256;
            int row = c >> 2, k4 = c & 3;
            float4 a = make_float4(0.f, 0.f, 0.f, 0.f);
            if (m0 + row < M)
                a = *(const float4*)&A[(size_t)(m0 + row) * K + k0 + k4 * 4];
            As[k4 * 4 + 0][row] = a.x;
            As[k4 * 4 + 1][row] = a.y;
            As[k4 * 4 + 2][row] = a.z;
            As[k4 * 4 + 3][row] = a.w;
        }
        // load B tile: 16 k x 128 cols = 512 float4; 2 per thread
#pragma unroll
        for (int l = 0; l < 2; l++) {
            int c = t + l * 256;
            int kk = c >> 5, col4 = c & 31;
            float4 b = *(const float4*)&B[(size_t)(k0 + kk) * N + n0 + col4 * 4];
            *(float4*)&Bs[kk][col4 * 4] = b;
        }
        __syncthreads();
#pragma unroll
        for (int k = 0; k < 16; k++) {
            float4 a0 = *(const float4*)&As[k][tm * 4];
            float4 a1 = *(const float4*)&As[k][64 + tm * 4];
            float4 b0 = *(const float4*)&Bs[k][tn * 4];
            float4 b1 = *(const float4*)&Bs[k][64 + tn * 4];
            float am[8] = {a0.x, a0.y, a0.z, a0.w, a1.x, a1.y, a1.z, a1.w};
            float bn[8] = {b0.x, b0.y, b0.z, b0.w, b1.x, b1.y, b1.z, b1.w};
#pragma unroll
            for (int i = 0; i < 8; i++)
#pragma unroll
                for (int j = 0; j < 8; j++)
                    acc[i][j] = fmaf(am[i], bn[j], acc[i][j]);
        }
        __syncthreads();
    }

    float bb[8] = {};
    if (bias) {
        float4 c0 = *(const float4*)&bias[n0 + tn * 4];
        float4 c1 = *(const float4*)&bias[n0 + 64 + tn * 4];
        bb[0] = c0.x; bb[1] = c0.y; bb[2] = c0.z; bb[3] = c0.w;
        bb[4] = c1.x; bb[5] = c1.y; bb[6] = c1.z; bb[7] = c1.w;
    }
#pragma unroll
    for (int i = 0; i < 8; i++) {
        int m = m0 + ((i < 4) ? (tm * 4 + i) : (64 + tm * 4 + i - 4));
        if (m >= M) continue;
        float r[8];
#pragma unroll
        for (int j = 0; j < 8; j++) {
            r[j] = acc[i][j] + bb[j];
            if (doSelu) r[j] = selu_f(r[j]);
        }
        *(float4*)&C[(size_t)m * N + n0 + tn * 4] =
            make_float4(r[0], r[1], r[2], r[3]);
        *(float4*)&C[(size_t)m * N + n0 + 64 + tn * 4] =
            make_float4(r[4], r[5], r[6], r[7]);
    }
}

// ---------------------------- epilogue kernels -----------------------------
__global__ void selu_colsum_kernel(const float* __restrict__ S2,
                                   const float* __restrict__ b2,
                                   float* __restrict__ colsum, int M) {
    int t = threadIdx.x;  // 0..127
    int r0 = blockIdx.x * 128;
    int rend = min(r0 + 128, M);
    float b = b2[t];
    float s = 0.f;
    for (int r = r0; r < rend; r++)
        s += selu_f(S2[(size_t)r * 128 + t] + b);
    atomicAdd(&colsum[t], s);
}

__global__ void final_kernel(const float* __restrict__ colsum,
                             const float* __restrict__ sub_fea,
                             const float* __restrict__ Wf,
                             const float* __restrict__ bf,
                             float* __restrict__ out, int M) {
    __shared__ float gcat[192];
    __shared__ float sred[4];
    int t = threadIdx.x;  // 0..127
    gcat[t] = selu_f(colsum[t] / (float)M);
    if (t < 64) gcat[128 + t] = sub_fea[t];
    __syncthreads();

    float logit = bf[t];
#pragma unroll 8
    for (int i = 0; i < 192; i++)
        logit = fmaf(gcat[i], Wf[i * 128 + t], logit);

    float mx = logit;
    for (int o = 16; o; o >>= 1) mx = fmaxf(mx, __shfl_xor_sync(0xffffffffu, mx, o));
    if ((t & 31) == 0) sred[t >> 5] = mx;
    __syncthreads();
    mx = fmaxf(fmaxf(sred[0], sred[1]), fmaxf(sred[2], sred[3]));
    __syncthreads();

    float e = expf(logit - mx);
    float se = e;
    for (int o = 16; o; o >>= 1) se += __shfl_xor_sync(0xffffffffu, se, o);
    if ((t & 31) == 0) sred[t >> 5] = se;
    __syncthreads();
    se = sred[0] + sred[1] + sred[2] + sred[3];
    out[t] = logit - mx - logf(se);
    __syncthreads();

    float l = 0.f;
    for (int i = t; i < 24576; i += 128) l += fabsf(Wf[i]);
    for (int o = 16; o; o >>= 1) l += __shfl_xor_sync(0xffffffffu, l, o);
    if ((t & 31) == 0) sred[t >> 5] = l;
    __syncthreads();
    if (t == 0) out[128] = (sred[0] + sred[1] + sred[2] + sred[3]) / 24576.0f;
}

// ---------------------------------------------------------------------------
extern "C" void kernel_launch(void* const* d_in, const int* in_sizes, int n_in,
                              void* d_out, int out_size) {
    const float* x       = (const float*)d_in[0];
    const int*   adj     = (const int*)  d_in[1];
    const float* vals    = (const float*)d_in[2];
    const float* sub_fea = (const float*)d_in[3];
    const float* W1      = (const float*)d_in[4];
    const float* b1      = (const float*)d_in[5];
    const float* W2      = (const float*)d_in[6];
    const float* b2      = (const float*)d_in[7];
    const float* Wf      = (const float*)d_in[8];
    const float* bf      = (const float*)d_in[9];
    float* out = (float*)d_out;

    int E = in_sizes[2];
    int M = in_sizes[0] / 256;

    float *pAX, *pH1, *pH2, *pS2, *pCS;
    int *pCount, *pCursor;
    cudaGetSymbolAddress((void**)&pAX, g_AX);
    cudaGetSymbolAddress((void**)&pH1, g_H1);
    cudaGetSymbolAddress((void**)&pH2, g_H2);
    cudaGetSymbolAddress((void**)&pS2, g_S2);
    cudaGetSymbolAddress((void**)&pCS, g_CS);
    cudaGetSymbolAddress((void**)&pCount, g_count);
    cudaGetSymbolAddress((void**)&pCursor, g_cursor);

    cudaMemsetAsync(pCount, 0, M * sizeof(int));
    cudaMemsetAsync(pCursor, 0, M * sizeof(int));
    cudaMemsetAsync(pCS, 0, 128 * sizeof(float));

    // CSR build (shared by both SpMMs)
    hist_kernel<<<(E + 255) / 256, 256>>>(adj, E);
    scan_kernel<<<1, 1024>>>(M, E);
    scatter_kernel<<<(E + 255) / 256, 256>>>(adj, adj + E, vals, E);

    int spmmGrid = (M + 7) / 8;
    // AX = spmm(adj, x)  [M,256]
    spmm_csr_kernel<256><<<spmmGrid, 256>>>(x, pAX, M);
    // h1 = selu(AX @ W1 + b1)  [M,512]
    dim3 g1(512 / 128, (M + 127) / 128);
    gemm128_kernel<<<g1, 256>>>(pAX, W1, b1, pH1, M, 512, 256, 1);
    // H2 = h1 @ W2  [M,128]
    dim3 g2(128 / 128, (M + 127) / 128);
    gemm128_kernel<<<g2, 256>>>(pH1, W2, nullptr, pH2, M, 128, 512, 0);
    // S2 = spmm(adj, H2)  [M,128]
    spmm_csr_kernel<128><<<spmmGrid, 256>>>(pH2, pS2, M);
    // colsum(selu(S2 + b2))
    selu_colsum_kernel<<<(M + 127) / 128, 128>>>(pS2, b2, pCS, M);
    // head
    final_kernel<<<1, 128>>>(pCS, sub_fea, Wf, bf, out, M);
}